// round 7
// baseline (speedup 1.0000x reference)
#include <cuda_runtime.h>
#include <cstdint>

#define BB  4
#define SS  2048
#define DD  768
#define NHH 4
#define DHH 192
#define KW  4

// ---------------- scratch (device globals; no allocation allowed) ----------------
__device__ float g_XC[(size_t)BB * SS * DD];                    // conv+swish output
__device__ float g_G[(size_t)BB * NHH * 4 * SS * DHH];          // gate preactivations [b][h][g][s][e]
__device__ float g_Y[(size_t)BB * SS * DD];                     // scan output (pre-LN)

// ---------------- small PTX helpers ----------------
__device__ __forceinline__ unsigned smem_u32(const void* p) {
    return (unsigned)__cvta_generic_to_shared(p);
}
__device__ __forceinline__ unsigned mapa_sh(unsigned addr, unsigned rank) {
    unsigned r;
    asm("mapa.shared::cluster.u32 %0, %1, %2;" : "=r"(r) : "r"(addr), "r"(rank));
    return r;
}
// single 8B relaxed store to a (possibly remote) cluster smem address
__device__ __forceinline__ void st_pair_cluster(unsigned addr, unsigned long long p) {
    asm volatile("st.relaxed.cluster.shared::cluster.b64 [%0], %1;"
                 :: "r"(addr), "l"(p) : "memory");
}
// 8B relaxed load from local smem
__device__ __forceinline__ unsigned long long ld_pair(unsigned addr) {
    unsigned long long p;
    asm volatile("ld.relaxed.cluster.shared::cta.b64 %0, [%1];"
                 : "=l"(p) : "r"(addr) : "memory");
    return p;
}
__device__ __forceinline__ void cluster_sync_all() {
    asm volatile("barrier.cluster.arrive.aligned;" ::: "memory");
    asm volatile("barrier.cluster.wait.aligned;" ::: "memory");
}
// packed dual fp32 FMA (Blackwell f32x2)
__device__ __forceinline__ float2 ffma2(float2 a, float2 b, float2 c) {
    float2 d;
    asm("fma.rn.f32x2 %0, %1, %2, %3;"
        : "=l"(reinterpret_cast<unsigned long long&>(d))
        : "l"(reinterpret_cast<unsigned long long&>(a)),
          "l"(reinterpret_cast<unsigned long long&>(b)),
          "l"(reinterpret_cast<unsigned long long&>(c)));
    return d;
}
// duplicate a scalar into both halves of an f32x2
__device__ __forceinline__ float2 dup2(float a) {
    float2 d;
    asm("mov.b64 %0, {%1, %1};"
        : "=l"(reinterpret_cast<unsigned long long&>(d)) : "f"(a));
    return d;
}

// ---------------- 1) causal depthwise conv + swish ----------------
__global__ __launch_bounds__(256) void conv_swish_kernel(
    const float* __restrict__ X, const float* __restrict__ CK, const float* __restrict__ CB)
{
    int idx = blockIdx.x * 256 + threadIdx.x;
    if (idx >= BB * SS * DD) return;
    int d  = idx % DD;
    int bs = idx / DD;
    int s  = bs % SS;
    float acc = CB[d];
#pragma unroll
    for (int j = 0; j < KW; j++) {
        int sp = s + j - (KW - 1);
        if (sp >= 0) acc = fmaf(CK[j * DD + d], X[idx + (j - (KW - 1)) * DD], acc);
    }
    g_XC[idx] = acc / (1.f + __expf(-acc));   // swish
}

// ---------------- 2) gate projections: 64 GEMMs (2048x192 @ 192x192) ----------------
#define GBM 128
#define GBN 96
#define GBK 32
#define AS_STRIDE 129   // padded: conflict-free STS, broadcast LDS

__global__ __launch_bounds__(256) void gemm_gates_kernel(
    const float* __restrict__ X,
    const float* __restrict__ Wi, const float* __restrict__ Wf,
    const float* __restrict__ Wz, const float* __restrict__ Wo)
{
    __shared__ float As[GBK * AS_STRIDE];
    __shared__ float Bs[GBK][GBN];

    int z = blockIdx.z;               // b*16 + h*4 + g
    int b = z >> 4, h = (z >> 2) & 3, g = z & 3;
    int m0 = blockIdx.x * GBM;
    int n0 = blockIdx.y * GBN;

    const float* A = ((g < 2) ? g_XC : X) + (size_t)b * SS * DD + h * DHH;  // row stride DD
    const float* W = ((g == 0) ? Wi : (g == 1) ? Wf : (g == 2) ? Wz : Wo) + (size_t)h * DHH * DHH;
    float* C = g_G + (size_t)z * SS * DHH;

    int tid = threadIdx.x;
    int tm = (tid >> 4) * 8;          // 16 groups x 8 rows
    int tn = (tid & 15) * 6;          // 16 groups x 6 cols

    float2 acc[8][3];
#pragma unroll
    for (int i = 0; i < 8; i++)
#pragma unroll
        for (int j = 0; j < 3; j++) acc[i][j] = make_float2(0.f, 0.f);

    for (int k0 = 0; k0 < DHH; k0 += GBK) {
        // load A tile 128x32 (float4, coalesced), store transposed As[k][m]
#pragma unroll
        for (int t = 0; t < 4; t++) {
            int i4 = t * 256 + tid;
            int m = i4 >> 3, kq = i4 & 7;
            float4 v = *(const float4*)(A + (size_t)(m0 + m) * DD + k0 + kq * 4);
            As[(kq * 4 + 0) * AS_STRIDE + m] = v.x;
            As[(kq * 4 + 1) * AS_STRIDE + m] = v.y;
            As[(kq * 4 + 2) * AS_STRIDE + m] = v.z;
            As[(kq * 4 + 3) * AS_STRIDE + m] = v.w;
        }
        // load B tile 32x96 (float4)
#pragma unroll
        for (int t = 0; t < 3; t++) {
            int i4 = t * 256 + tid;
            int kk = i4 / 24, nq = i4 % 24;
            float4 v = *(const float4*)(W + (size_t)(k0 + kk) * DHH + n0 + nq * 4);
            *(float4*)&Bs[kk][nq * 4] = v;
        }
        __syncthreads();
#pragma unroll
        for (int k = 0; k < GBK; k++) {
            float2 b2[3];
#pragma unroll
            for (int j = 0; j < 3; j++) b2[j] = *(const float2*)&Bs[k][tn + 2 * j];
#pragma unroll
            for (int i = 0; i < 8; i++) {
                float2 ad = dup2(As[k * AS_STRIDE + tm + i]);
#pragma unroll
                for (int j = 0; j < 3; j++) acc[i][j] = ffma2(ad, b2[j], acc[i][j]);
            }
        }
        __syncthreads();
    }
#pragma unroll
    for (int i = 0; i < 8; i++)
#pragma unroll
        for (int j = 0; j < 3; j++)
            *(float2*)(C + (size_t)(m0 + tm + i) * DHH + n0 + tn + 2 * j) = acc[i][j];
}

// ---------------- 3) sequential sLSTM scan ----------------
// 16 clusters of 4 CTAs; cluster = one (b,h). CTA rank r owns output slice
// e in [r*48, r*48+48) of ALL four gates. h is exchanged via DSMEM as
// tagged 8-byte {value, step} pairs — no flags, no release/acquire, no
// producer-side ordering stall. Consumers poll local tags (cheap LDS).
__global__ __launch_bounds__(384, 1) __cluster_dims__(4, 1, 1)
void scan_kernel(const float* __restrict__ R, const float* __restrict__ CBIAS)
{
    // hpair[buf][e] = {h value (.x), step tag (.y as uint)}
    __shared__ __align__(16) float2 hpair[2][DHH];
    __shared__ float sh_pre[DHH];                  // [g*48 + j] rec+gate+bias

    int tid = threadIdx.x;
    int cid = blockIdx.x >> 2;     // (b*NH + h)
    int b = cid >> 2;
    int h = cid & 3;
    int r = blockIdx.x & 3;        // cluster rank
    int e0 = r * 48;

    int out = tid >> 1;            // 0..191 : g*48 + j
    int kh  = tid & 1;             // k half
    int g   = out / 48;
    int j   = out % 48;
    int e   = e0 + j;
    int kbase = kh * 96;

    // register-resident recurrent weights: pairs {R[k][e], R[k+1][e]}
    float2 w[48];
    {
        const float* Rb = R + ((size_t)(g * NHH + h)) * DHH * DHH + e;
#pragma unroll
        for (int i = 0; i < 48; i++) {
            w[i].x = Rb[(size_t)(kbase + 2 * i) * DHH];
            w[i].y = Rb[(size_t)(kbase + 2 * i + 1) * DHH];
        }
    }
    float biasr = CBIAS[g * DD + h * DHH + e];

    const float* gptr = g_G + ((size_t)(cid * 4 + g)) * SS * DHH + e;
    float* ybase = g_Y + (size_t)b * SS * DD + h * DHH + e0;

    // per-thread scan state (only meaningful for tid < 48)
    float c_r = 0.f, n_r = 0.f, m_r = 0.f;

    // init both buffers: value 0, tag 0  (tag 0 == h_0)
    for (int i = tid; i < DHH; i += 384) {
        hpair[0][i] = make_float2(0.f, __uint_as_float(0u));
        hpair[1][i] = make_float2(0.f, __uint_as_float(0u));
    }

    // producers: remote pair addresses (element e0+tid of hpair[0]) on all 4 ranks
    unsigned pa0 = 0, pa1 = 0, pa2 = 0, pa3 = 0;
    if (tid < 48) {
        unsigned a0 = smem_u32(&hpair[0][e0 + tid]);
        pa0 = mapa_sh(a0, 0);
        pa1 = mapa_sh(a0, 1);
        pa2 = mapa_sh(a0, 2);
        pa3 = mapa_sh(a0, 3);
    }
    // consumers: local poll address (thread t polls element t, t < 192)
    unsigned poll_a = smem_u32(&hpair[0][tid < DHH ? tid : 0]);

    __syncthreads();
    cluster_sync_all();   // zeroed tagged buffers visible cluster-wide

    // 2-deep gate-preactivation prefetch (load-to-use > DRAM latency)
    float g0 = gptr[0];
    float g1 = gptr[DHH];

    const unsigned BUFBYTES = DHH * 8;

    for (int s = 0; s < SS; s++) {
        int cur = s & 1;

        // ---- wait for h_s (tag >= s) on owned poll slot, then CTA-wide bar ----
        if (tid < DHH) {
            unsigned a = poll_a + (unsigned)cur * BUFBYTES;
            while ((unsigned)(ld_pair(a) >> 32) < (unsigned)s) { }
        }
        __syncthreads();                                  // all pairs of step s present

        int sp = (s + 2 < SS) ? s + 2 : SS - 1;
        float g2 = gptr[(size_t)sp * DHH];

        // ---- recurrent matvec: interleaved {v,tag,v,tag} float4 loads ----
        float2 a0 = make_float2(0.f, 0.f), a1 = a0, a2 = a0, a3 = a0;
        const float4* hp = (const float4*)&hpair[cur][kbase];
#pragma unroll
        for (int i = 0; i < 48; i += 4) {
            float4 p0 = hp[i],     p1 = hp[i + 1];
            float4 p2 = hp[i + 2], p3 = hp[i + 3];
            a0 = ffma2(make_float2(p0.x, p0.z), w[i],     a0);
            a1 = ffma2(make_float2(p1.x, p1.z), w[i + 1], a1);
            a2 = ffma2(make_float2(p2.x, p2.z), w[i + 2], a2);
            a3 = ffma2(make_float2(p3.x, p3.z), w[i + 3], a3);
        }
        float part = ((a0.x + a1.x) + (a0.y + a1.y)) + ((a2.x + a3.x) + (a2.y + a3.y));
        part += __shfl_xor_sync(0xffffffffu, part, 1);   // combine k halves
        if (kh == 0) sh_pre[out] = part + g0 + biasr;
        g0 = g1; g1 = g2;
        __syncthreads();                                  // sh_pre ready

        // ---- elementwise stabilized exponential gating (local slice) ----
        if (tid < 48) {
            float it = sh_pre[tid];
            float ft = sh_pre[48 + tid];
            float zt = sh_pre[96 + tid];
            float ot = sh_pre[144 + tid];
            float fm = ft + m_r;
            float mn = fmaxf(fm, it);
            float ia = __expf(it - mn);
            float fa = __expf(fm - mn);
            float th = 1.f - 2.f / (__expf(2.f * zt) + 1.f);       // tanh
            float cn = fa * c_r + ia * th;
            float nn = fa * n_r + ia;
            float hv = cn / ((1.f + __expf(-ot)) * nn);            // sigmoid(ot)*cn/nn
            c_r = cn; n_r = nn; m_r = mn;

            // ship {value, tag=s+1} as one atomic 8B store to all 4 ranks
            unsigned long long p =
                ((unsigned long long)(unsigned)(s + 1) << 32) | (unsigned long long)__float_as_uint(hv);
            unsigned off = (unsigned)((s + 1) & 1) * BUFBYTES;
            st_pair_cluster(pa0 + off, p);
            st_pair_cluster(pa1 + off, p);
            st_pair_cluster(pa2 + off, p);
            st_pair_cluster(pa3 + off, p);

            ybase[(size_t)s * DD + tid] = hv;          // pre-LN output
        }
        // no trailing bar: next iteration's poll+bar provides the sync
    }
}

// ---------------- 4) multi-head layernorm ----------------
__global__ __launch_bounds__(256) void ln_kernel(const float* __restrict__ GS, float* __restrict__ OUT)
{
    int w = blockIdx.x * 8 + (threadIdx.x >> 5);   // (b*S+s)*NH + h
    int lane = threadIdx.x & 31;
    int h = w & 3;
    int bs = w >> 2;
    const float* yp = g_Y + (size_t)bs * DD + h * DHH;

    float v[6], sum = 0.f, sq = 0.f;
#pragma unroll
    for (int i = 0; i < 6; i++) {
        v[i] = yp[i * 32 + lane];
        sum += v[i];
        sq  = fmaf(v[i], v[i], sq);
    }
#pragma unroll
    for (int o = 16; o > 0; o >>= 1) {
        sum += __shfl_xor_sync(0xffffffffu, sum, o);
        sq  += __shfl_xor_sync(0xffffffffu, sq,  o);
    }
    float mean = sum * (1.f / 192.f);
    float var  = sq * (1.f / 192.f) - mean * mean;
    float inv  = rsqrtf(var + 1e-5f);
    float* op = OUT + (size_t)bs * DD + h * DHH;
#pragma unroll
    for (int i = 0; i < 6; i++)
        op[i * 32 + lane] = (v[i] - mean) * inv * GS[h * DHH + i * 32 + lane];
}

// ---------------- launch ----------------
extern "C" void kernel_launch(void* const* d_in, const int* in_sizes, int n_in,
                              void* d_out, int out_size)
{
    const float* x     = (const float*)d_in[0];
    const float* ck    = (const float*)d_in[1];
    const float* cb    = (const float*)d_in[2];
    const float* Wi    = (const float*)d_in[3];
    const float* Wf    = (const float*)d_in[4];
    const float* Wz    = (const float*)d_in[5];
    const float* Wo    = (const float*)d_in[6];
    const float* R     = (const float*)d_in[7];
    const float* cbias = (const float*)d_in[8];
    const float* gs    = (const float*)d_in[9];
    float* out = (float*)d_out;

    conv_swish_kernel<<<(BB * SS * DD + 255) / 256, 256>>>(x, ck, cb);
    gemm_gates_kernel<<<dim3(SS / GBM, DHH / GBN, BB * NHH * 4), 256>>>(x, Wi, Wf, Wz, Wo);
    scan_kernel<<<BB * NHH * 4, 384>>>(R, cbias);
    ln_kernel<<<(BB * SS * NHH) / 8, 256>>>(gs, out);
}

// round 11
// speedup vs baseline: 1.9405x; 1.9405x over previous
#include <cuda_runtime.h>
#include <cstdint>

#define BB  4
#define SS  2048
#define DD  768
#define NHH 4
#define DHH 192
#define KW  4

// ---------------- scratch (device globals; no allocation allowed) ----------------
__device__ float g_XC[(size_t)BB * SS * DD];                    // conv+swish output
__device__ float g_G[(size_t)BB * NHH * 4 * SS * DHH];          // gate preactivations [b][h][g][s][e]
__device__ float g_Y[(size_t)BB * SS * DD];                     // scan output (pre-LN)

// ---------------- small PTX helpers ----------------
__device__ __forceinline__ unsigned smem_u32(const void* p) {
    return (unsigned)__cvta_generic_to_shared(p);
}
__device__ __forceinline__ unsigned mapa_sh(unsigned addr, unsigned rank) {
    unsigned r;
    asm("mapa.shared::cluster.u32 %0, %1, %2;" : "=r"(r) : "r"(addr), "r"(rank));
    return r;
}
// single 8B relaxed store to a (possibly remote) cluster smem address
__device__ __forceinline__ void st_pair_cluster(unsigned addr, unsigned long long p) {
    asm volatile("st.relaxed.cluster.shared::cluster.b64 [%0], %1;"
                 :: "r"(addr), "l"(p) : "memory");
}
// 8B relaxed load from local smem
__device__ __forceinline__ unsigned long long ld_pair(unsigned addr) {
    unsigned long long p;
    asm volatile("ld.relaxed.cluster.shared::cta.b64 %0, [%1];"
                 : "=l"(p) : "r"(addr) : "memory");
    return p;
}
__device__ __forceinline__ void cluster_sync_all() {
    asm volatile("barrier.cluster.arrive.aligned;" ::: "memory");
    asm volatile("barrier.cluster.wait.aligned;" ::: "memory");
}
// packed dual fp32 FMA (Blackwell f32x2)
__device__ __forceinline__ float2 ffma2(float2 a, float2 b, float2 c) {
    float2 d;
    asm("fma.rn.f32x2 %0, %1, %2, %3;"
        : "=l"(reinterpret_cast<unsigned long long&>(d))
        : "l"(reinterpret_cast<unsigned long long&>(a)),
          "l"(reinterpret_cast<unsigned long long&>(b)),
          "l"(reinterpret_cast<unsigned long long&>(c)));
    return d;
}
// duplicate a scalar into both halves of an f32x2
__device__ __forceinline__ float2 dup2(float a) {
    float2 d;
    asm("mov.b64 %0, {%1, %1};"
        : "=l"(reinterpret_cast<unsigned long long&>(d)) : "f"(a));
    return d;
}

// ---------------- 1) causal depthwise conv + swish ----------------
__global__ __launch_bounds__(256) void conv_swish_kernel(
    const float* __restrict__ X, const float* __restrict__ CK, const float* __restrict__ CB)
{
    int idx = blockIdx.x * 256 + threadIdx.x;
    if (idx >= BB * SS * DD) return;
    int d  = idx % DD;
    int bs = idx / DD;
    int s  = bs % SS;
    float acc = CB[d];
#pragma unroll
    for (int j = 0; j < KW; j++) {
        int sp = s + j - (KW - 1);
        if (sp >= 0) acc = fmaf(CK[j * DD + d], X[idx + (j - (KW - 1)) * DD], acc);
    }
    g_XC[idx] = acc / (1.f + __expf(-acc));   // swish
}

// ---------------- 2) gate projections: 64 GEMMs (2048x192 @ 192x192) ----------------
#define GBM 128
#define GBN 96
#define GBK 32
#define AS_STRIDE 129   // padded: conflict-free STS, broadcast LDS

__global__ __launch_bounds__(256) void gemm_gates_kernel(
    const float* __restrict__ X,
    const float* __restrict__ Wi, const float* __restrict__ Wf,
    const float* __restrict__ Wz, const float* __restrict__ Wo)
{
    __shared__ float As[GBK * AS_STRIDE];
    __shared__ float Bs[GBK][GBN];

    int z = blockIdx.z;               // b*16 + h*4 + g
    int b = z >> 4, h = (z >> 2) & 3, g = z & 3;
    int m0 = blockIdx.x * GBM;
    int n0 = blockIdx.y * GBN;

    const float* A = ((g < 2) ? g_XC : X) + (size_t)b * SS * DD + h * DHH;  // row stride DD
    const float* W = ((g == 0) ? Wi : (g == 1) ? Wf : (g == 2) ? Wz : Wo) + (size_t)h * DHH * DHH;
    float* C = g_G + (size_t)z * SS * DHH;

    int tid = threadIdx.x;
    int tm = (tid >> 4) * 8;          // 16 groups x 8 rows
    int tn = (tid & 15) * 6;          // 16 groups x 6 cols

    float2 acc[8][3];
#pragma unroll
    for (int i = 0; i < 8; i++)
#pragma unroll
        for (int j = 0; j < 3; j++) acc[i][j] = make_float2(0.f, 0.f);

    for (int k0 = 0; k0 < DHH; k0 += GBK) {
        // load A tile 128x32 (float4, coalesced), store transposed As[k][m]
#pragma unroll
        for (int t = 0; t < 4; t++) {
            int i4 = t * 256 + tid;
            int m = i4 >> 3, kq = i4 & 7;
            float4 v = *(const float4*)(A + (size_t)(m0 + m) * DD + k0 + kq * 4);
            As[(kq * 4 + 0) * AS_STRIDE + m] = v.x;
            As[(kq * 4 + 1) * AS_STRIDE + m] = v.y;
            As[(kq * 4 + 2) * AS_STRIDE + m] = v.z;
            As[(kq * 4 + 3) * AS_STRIDE + m] = v.w;
        }
        // load B tile 32x96 (float4)
#pragma unroll
        for (int t = 0; t < 3; t++) {
            int i4 = t * 256 + tid;
            int kk = i4 / 24, nq = i4 % 24;
            float4 v = *(const float4*)(W + (size_t)(k0 + kk) * DHH + n0 + nq * 4);
            *(float4*)&Bs[kk][nq * 4] = v;
        }
        __syncthreads();
#pragma unroll
        for (int k = 0; k < GBK; k++) {
            float2 b2[3];
#pragma unroll
            for (int j = 0; j < 3; j++) b2[j] = *(const float2*)&Bs[k][tn + 2 * j];
#pragma unroll
            for (int i = 0; i < 8; i++) {
                float2 ad = dup2(As[k * AS_STRIDE + tm + i]);
#pragma unroll
                for (int j = 0; j < 3; j++) acc[i][j] = ffma2(ad, b2[j], acc[i][j]);
            }
        }
        __syncthreads();
    }
#pragma unroll
    for (int i = 0; i < 8; i++)
#pragma unroll
        for (int j = 0; j < 3; j++)
            *(float2*)(C + (size_t)(m0 + tm + i) * DHH + n0 + tn + 2 * j) = acc[i][j];
}

// ---------------- 3) sequential sLSTM scan ----------------
// 16 clusters of 4 CTAs; cluster = one (b,h). CTA rank r owns output slice
// e in [r*48, r*48+48) of ALL four gates. h is exchanged via DSMEM as
// tagged 8-byte {value, step} pairs (single-copy atomic -> no flags, no
// release ordering). Each step, poll threads copy arrived values into a
// compact PADDED value array so the matvec's dual-broadcast LDS.128 hits
// disjoint bank groups (even lanes banks {4i..4i+3}, odd {4i+4..4i+7}).
#define HPAD 100   // float offset of kh=1 half in compact array (96 + 4 pad)

__global__ __launch_bounds__(384, 1) __cluster_dims__(4, 1, 1)
void scan_kernel(const float* __restrict__ R, const float* __restrict__ CBIAS)
{
    __shared__ __align__(16) float2 hpair[2][DHH];    // transport: {value, tag}
    __shared__ __align__(16) float sh_h[2][2 * HPAD]; // compute: compact values, padded halves
    __shared__ float sh_pre[DHH];                     // [g*48 + j] rec+gate+bias

    int tid = threadIdx.x;
    int cid = blockIdx.x >> 2;     // (b*NH + h)
    int b = cid >> 2;
    int h = cid & 3;
    int r = blockIdx.x & 3;        // cluster rank
    int e0 = r * 48;

    int out = tid >> 1;            // 0..191 : g*48 + j
    int kh  = tid & 1;             // k half
    int g   = out / 48;
    int j   = out % 48;
    int e   = e0 + j;
    int kbase = kh * 96;           // k index of this half

    // register-resident recurrent weights: pairs {R[k][e], R[k+1][e]}
    float2 w[48];
    {
        const float* Rb = R + ((size_t)(g * NHH + h)) * DHH * DHH + e;
#pragma unroll
        for (int i = 0; i < 48; i++) {
            w[i].x = Rb[(size_t)(kbase + 2 * i) * DHH];
            w[i].y = Rb[(size_t)(kbase + 2 * i + 1) * DHH];
        }
    }
    float biasr = CBIAS[g * DD + h * DHH + e];

    const float* gptr = g_G + ((size_t)(cid * 4 + g)) * SS * DHH + e;
    float* ybase = g_Y + (size_t)b * SS * DD + h * DHH + e0;

    // per-thread scan state (only meaningful for tid < 48)
    float c_r = 0.f, n_r = 0.f, m_r = 0.f;

    // init transport: value 0, tag 0  (tag 0 == h_0)
    for (int i = tid; i < DHH; i += 384) {
        hpair[0][i] = make_float2(0.f, __uint_as_float(0u));
        hpair[1][i] = make_float2(0.f, __uint_as_float(0u));
    }

    // producers: remote pair addresses (element e0+tid of hpair[0]) on all 4 ranks
    unsigned pa0 = 0, pa1 = 0, pa2 = 0, pa3 = 0;
    if (tid < 48) {
        unsigned a0 = smem_u32(&hpair[0][e0 + tid]);
        pa0 = mapa_sh(a0, 0);
        pa1 = mapa_sh(a0, 1);
        pa2 = mapa_sh(a0, 2);
        pa3 = mapa_sh(a0, 3);
    }
    // consumers: thread t (<192) polls pair t, writes compact slot (padded)
    int cslot = (tid < 96) ? tid : (tid + 4);          // +4-float pad between halves
    unsigned poll_a = smem_u32(&hpair[0][tid < DHH ? tid : 0]);

    __syncthreads();
    cluster_sync_all();   // zeroed tagged buffers visible cluster-wide

    // 2-deep gate-preactivation prefetch (load-to-use > DRAM latency)
    float g0 = gptr[0];
    float g1 = gptr[DHH];

    const unsigned BUFBYTES = DHH * 8;

    for (int s = 0; s < SS; s++) {
        int cur = s & 1;

        // ---- wait for h_s (tag >= s) and copy value into compact padded array ----
        if (tid < DHH) {
            unsigned a = poll_a + (unsigned)cur * BUFBYTES;
            unsigned long long p = ld_pair(a);
            while ((unsigned)(p >> 32) < (unsigned)s) p = ld_pair(a);
            sh_h[cur][cslot] = __uint_as_float((unsigned)p);
        }
        __syncthreads();                                  // all h_s values staged

        int sp = (s + 2 < SS) ? s + 2 : SS - 1;
        float g2 = gptr[(size_t)sp * DHH];

        // ---- recurrent matvec: conflict-free dual-broadcast LDS.128 ----
        float2 a0 = make_float2(0.f, 0.f), a1 = a0, a2 = a0, a3 = a0;
        const float4* hp = (const float4*)&sh_h[cur][kh * HPAD];
#pragma unroll
        for (int i = 0; i < 24; i += 2) {
            float4 h0 = hp[i], h1 = hp[i + 1];
            a0 = ffma2(make_float2(h0.x, h0.y), w[2 * i],     a0);
            a1 = ffma2(make_float2(h0.z, h0.w), w[2 * i + 1], a1);
            a2 = ffma2(make_float2(h1.x, h1.y), w[2 * i + 2], a2);
            a3 = ffma2(make_float2(h1.z, h1.w), w[2 * i + 3], a3);
        }
        float part = ((a0.x + a1.x) + (a0.y + a1.y)) + ((a2.x + a3.x) + (a2.y + a3.y));
        part += __shfl_xor_sync(0xffffffffu, part, 1);   // combine k halves
        if (kh == 0) sh_pre[out] = part + g0 + biasr;
        g0 = g1; g1 = g2;
        __syncthreads();                                  // sh_pre ready

        // ---- elementwise stabilized exponential gating (local slice) ----
        if (tid < 48) {
            float it = sh_pre[tid];
            float ft = sh_pre[48 + tid];
            float zt = sh_pre[96 + tid];
            float ot = sh_pre[144 + tid];
            float fm = ft + m_r;
            float mn = fmaxf(fm, it);
            float ia = __expf(it - mn);
            float fa = __expf(fm - mn);
            float th = 1.f - 2.f / (__expf(2.f * zt) + 1.f);       // tanh
            float cn = fa * c_r + ia * th;
            float nn = fa * n_r + ia;
            float hv = cn / ((1.f + __expf(-ot)) * nn);            // sigmoid(ot)*cn/nn
            c_r = cn; n_r = nn; m_r = mn;

            // ship {value, tag=s+1} as one atomic 8B store to all 4 ranks
            unsigned long long p =
                ((unsigned long long)(unsigned)(s + 1) << 32) | (unsigned long long)__float_as_uint(hv);
            unsigned off = (unsigned)((s + 1) & 1) * BUFBYTES;
            st_pair_cluster(pa0 + off, p);
            st_pair_cluster(pa1 + off, p);
            st_pair_cluster(pa2 + off, p);
            st_pair_cluster(pa3 + off, p);

            ybase[(size_t)s * DD + tid] = hv;          // pre-LN output
        }
        // no trailing bar: next iteration's poll+bar provides the sync
    }

    cluster_sync_all();   // don't exit while peer stores may be in flight
}

// ---------------- 4) multi-head layernorm ----------------
__global__ __launch_bounds__(256) void ln_kernel(const float* __restrict__ GS, float* __restrict__ OUT)
{
    int w = blockIdx.x * 8 + (threadIdx.x >> 5);   // (b*S+s)*NH + h
    int lane = threadIdx.x & 31;
    int h = w & 3;
    int bs = w >> 2;
    const float* yp = g_Y + (size_t)bs * DD + h * DHH;

    float v[6], sum = 0.f, sq = 0.f;
#pragma unroll
    for (int i = 0; i < 6; i++) {
        v[i] = yp[i * 32 + lane];
        sum += v[i];
        sq  = fmaf(v[i], v[i], sq);
    }
#pragma unroll
    for (int o = 16; o > 0; o >>= 1) {
        sum += __shfl_xor_sync(0xffffffffu, sum, o);
        sq  += __shfl_xor_sync(0xffffffffu, sq,  o);
    }
    float mean = sum * (1.f / 192.f);
    float var  = sq * (1.f / 192.f) - mean * mean;
    float inv  = rsqrtf(var + 1e-5f);
    float* op = OUT + (size_t)bs * DD + h * DHH;
#pragma unroll
    for (int i = 0; i < 6; i++)
        op[i * 32 + lane] = (v[i] - mean) * inv * GS[h * DHH + i * 32 + lane];
}

// ---------------- launch ----------------
extern "C" void kernel_launch(void* const* d_in, const int* in_sizes, int n_in,
                              void* d_out, int out_size)
{
    const float* x     = (const float*)d_in[0];
    const float* ck    = (const float*)d_in[1];
    const float* cb    = (const float*)d_in[2];
    const float* Wi    = (const float*)d_in[3];
    const float* Wf    = (const float*)d_in[4];
    const float* Wz    = (const float*)d_in[5];
    const float* Wo    = (const float*)d_in[6];
    const float* R     = (const float*)d_in[7];
    const float* cbias = (const float*)d_in[8];
    const float* gs    = (const float*)d_in[9];
    float* out = (float*)d_out;

    conv_swish_kernel<<<(BB * SS * DD + 255) / 256, 256>>>(x, ck, cb);
    gemm_gates_kernel<<<dim3(SS / GBM, DHH / GBN, BB * NHH * 4), 256>>>(x, Wi, Wf, Wz, Wo);
    scan_kernel<<<BB * NHH * 4, 384>>>(R, cbias);
    ln_kernel<<<(BB * SS * NHH) / 8, 256>>>(gs, out);
}